// round 15
// baseline (speedup 1.0000x reference)
#include <cuda_runtime.h>
#include <cstdint>

#define NTOK 4096            // d*h*w = 16^3
#define CCH  256             // channels
#define BATCH 2
#define GRP  32
#define CPG  (CCH/GRP)       // 8
#define EPSV 1e-6f
#define SCALE 0.0625f        // 256^-0.5

// ---------------- scratch (device globals; no allocation allowed) ----------
__device__ unsigned g_hnh[BATCH*CCH*NTOK];        // tf32 split of groupnorm out
__device__ unsigned g_hnl[BATCH*CCH*NTOK];
__device__ float    g_q [BATCH*CCH*NTOK];         // tf32-rounded, pre-scaled
__device__ float    g_k [BATCH*CCH*NTOK];         // tf32-rounded
__device__ float    g_v [BATCH*CCH*NTOK];         // tf32-rounded
__device__ unsigned g_hvh[BATCH*CCH*NTOK];        // tf32 split of v.attn^T
__device__ unsigned g_hvl[BATCH*CCH*NTOK];
__device__ unsigned g_wth[4*CCH*CCH];             // W transposed [k][o], tf32 hi
__device__ unsigned g_wtl[4*CCH*CCH];             //                      tf32 lo
__device__ float    g_p [(size_t)BATCH*NTOK*NTOK]; // exp(S), tf32-rounded
__device__ float    g_sum[BATCH*NTOK];
__device__ float    g_stats[BATCH*GRP*2];

// ---------------- helpers --------------------------------------------------
__device__ __forceinline__ unsigned f2tf(float f) {
    unsigned u;
    asm("cvt.rna.tf32.f32 %0, %1;" : "=r"(u) : "f"(f));
    return u;
}

__device__ __forceinline__ void mma8(float* c, const unsigned* a, const unsigned* b) {
    asm volatile(
        "mma.sync.aligned.m16n8k8.row.col.f32.tf32.tf32.f32 "
        "{%0,%1,%2,%3}, {%4,%5,%6,%7}, {%8,%9}, {%0,%1,%2,%3};\n"
        : "+f"(c[0]), "+f"(c[1]), "+f"(c[2]), "+f"(c[3])
        : "r"(a[0]), "r"(a[1]), "r"(a[2]), "r"(a[3]),
          "r"(b[0]), "r"(b[1]));
}

__device__ __forceinline__ void cpa16(void* smem, const void* gmem) {
    unsigned saddr = (unsigned)__cvta_generic_to_shared(smem);
    asm volatile("cp.async.cg.shared.global [%0], [%1], 16;\n" :: "r"(saddr), "l"(gmem));
}
#define CPA_COMMIT asm volatile("cp.async.commit_group;\n" ::: "memory")
#define CPA_WAIT1  asm volatile("cp.async.wait_group 1;\n" ::: "memory")
#define CPA_WAIT0  asm volatile("cp.async.wait_group 0;\n" ::: "memory")

// ---------------- W prep: transpose+split; also zeros accumulators ---------
__global__ void prep_w(const float* __restrict__ w0, const float* __restrict__ w1,
                       const float* __restrict__ w2, const float* __restrict__ w3)
{
    const int m = blockIdx.y;
    const float* W = (m == 0) ? w0 : (m == 1) ? w1 : (m == 2) ? w2 : w3;
    const int o = blockIdx.x;
    const int k = threadIdx.x;
    if (m == 0) {                          // fused zeroing (idx covers 0..65535)
        const int idx = o*256 + k;
        if (idx < BATCH*NTOK)  g_sum[idx]   = 0.f;
        if (idx < BATCH*GRP*2) g_stats[idx] = 0.f;
    }
    const float f = W[o*CCH + k];
    const unsigned h = f2tf(f);
    g_wth[m*CCH*CCH + k*CCH + o] = h;
    g_wtl[m*CCH*CCH + k*CCH + o] = f2tf(f - __uint_as_float(h));
}

// ---------------- GroupNorm pass 1: partial stats --------------------------
__global__ void gn_stats(const float* __restrict__ x)
{
    const int gidx  = blockIdx.x >> 3;
    const int chunk = blockIdx.x & 7;
    const float* xp = x + (size_t)gidx*CPG*NTOK + chunk*NTOK;
    const int tid = threadIdx.x;

    float s = 0.f, ss = 0.f;
    #pragma unroll
    for (int i = tid*4; i < NTOK; i += 1024) {
        float4 t = *(const float4*)(xp + i);
        s  += t.x + t.y + t.z + t.w;
        ss += t.x*t.x + t.y*t.y + t.z*t.z + t.w*t.w;
    }
    __shared__ float rs[256], rq[256];
    rs[tid] = s; rq[tid] = ss;
    __syncthreads();
    for (int off = 128; off; off >>= 1) {
        if (tid < off) { rs[tid] += rs[tid+off]; rq[tid] += rq[tid+off]; }
        __syncthreads();
    }
    if (tid == 0) {
        atomicAdd(&g_stats[2*gidx],   rs[0]);
        atomicAdd(&g_stats[2*gidx+1], rq[0]);
    }
}

// ---------------- GroupNorm pass 2: normalize + tf32-split write -----------
__global__ void gn_apply(const float* __restrict__ x,
                         const float* __restrict__ gamma,
                         const float* __restrict__ beta)
{
    const int c    = blockIdx.x & 255;
    const int gidx = (blockIdx.x >> 8) * GRP + (c >> 3);
    const float mu   = g_stats[2*gidx]   * (1.f/32768.f);
    const float var  = g_stats[2*gidx+1] * (1.f/32768.f) - mu*mu;
    const float rstd = rsqrtf(var + EPSV);
    const float ga = gamma[c]*rstd, be = beta[c];

    const size_t base = (size_t)blockIdx.x * NTOK;
    const int i = threadIdx.x * 4;
    #pragma unroll
    for (int s = 0; s < 4; s++) {
        float4 t = *(const float4*)(x + base + i + s*1024);
        float f[4];
        f[0] = (t.x - mu)*ga + be;
        f[1] = (t.y - mu)*ga + be;
        f[2] = (t.z - mu)*ga + be;
        f[3] = (t.w - mu)*ga + be;
        uint4 uh, ul;
        uh.x = f2tf(f[0]); ul.x = f2tf(f[0] - __uint_as_float(uh.x));
        uh.y = f2tf(f[1]); ul.y = f2tf(f[1] - __uint_as_float(uh.y));
        uh.z = f2tf(f[2]); ul.z = f2tf(f[2] - __uint_as_float(uh.z));
        uh.w = f2tf(f[3]); ul.w = f2tf(f[3] - __uint_as_float(uh.w));
        *(uint4*)(g_hnh + base + i + s*1024) = uh;
        *(uint4*)(g_hnl + base + i + s*1024) = ul;
    }
}

// ---------------- fused q/k/v projection; cp.async 2-stage, k-chunk 8 ------
__global__ void __launch_bounds__(256)
mm_qkv(const float* __restrict__ bq,
       const float* __restrict__ bk,
       const float* __restrict__ bv)
{
    const int b   = blockIdx.z;
    const int sel = blockIdx.y >> 1;
    const int o0  = (blockIdx.y & 1) * 128;
    const int n0  = blockIdx.x * 128;

    const unsigned* Wh  = g_wth + sel*CCH*CCH;
    const unsigned* Wl  = g_wtl + sel*CCH*CCH;
    const unsigned* Bhg = g_hnh + (size_t)b*CCH*NTOK;
    const unsigned* Blg = g_hnl + (size_t)b*CCH*NTOK;
    float* O = ((sel == 0) ? g_q : (sel == 1) ? g_k : g_v) + (size_t)b*CCH*NTOK;
    const float* bias = (sel == 0) ? bq : (sel == 1) ? bk : bv;
    const float outScale = (sel == 0) ? SCALE : 1.f;

    __shared__ unsigned Ah[2][8][136], Al[2][8][136];
    __shared__ unsigned Bh[2][8][136], Bl[2][8][136];

    const int tid  = threadIdx.x;
    const int lane = tid & 31;
    const int wid  = tid >> 5;
    const int wr   = (wid & 1) * 64;
    const int wc   = (wid >> 1) * 32;
    const int lq   = lane >> 2;
    const int lr   = lane & 3;

    const int kc = tid >> 5, c4 = (tid & 31) * 4;   // one 16B chunk per array

    float acc[4][4][4] = {};

    // prologue: stage 0
    cpa16(&Ah[0][kc][c4], Wh  + kc*CCH + o0 + c4);
    cpa16(&Al[0][kc][c4], Wl  + kc*CCH + o0 + c4);
    cpa16(&Bh[0][kc][c4], Bhg + (size_t)kc*NTOK + n0 + c4);
    cpa16(&Bl[0][kc][c4], Blg + (size_t)kc*NTOK + n0 + c4);
    CPA_COMMIT;

    for (int it = 0; it < 32; it++) {
        const int buf = it & 1;
        CPA_WAIT0;
        __syncthreads();
        if (it + 1 < 32) {
            const int k0 = (it + 1) * 8;
            cpa16(&Ah[buf^1][kc][c4], Wh  + (k0+kc)*CCH + o0 + c4);
            cpa16(&Al[buf^1][kc][c4], Wl  + (k0+kc)*CCH + o0 + c4);
            cpa16(&Bh[buf^1][kc][c4], Bhg + (size_t)(k0+kc)*NTOK + n0 + c4);
            cpa16(&Bl[buf^1][kc][c4], Blg + (size_t)(k0+kc)*NTOK + n0 + c4);
            CPA_COMMIT;
        }
        unsigned bh[4][2], bl[4][2];
        #pragma unroll
        for (int nt = 0; nt < 4; nt++) {
            int col = wc + nt*8 + lq;
            bh[nt][0] = Bh[buf][lr    ][col];
            bh[nt][1] = Bh[buf][4 + lr][col];
            bl[nt][0] = Bl[buf][lr    ][col];
            bl[nt][1] = Bl[buf][4 + lr][col];
        }
        #pragma unroll
        for (int mt = 0; mt < 4; mt++) {
            unsigned ah[4], al[4];
            int rb = wr + mt*16 + lq;
            ah[0] = Ah[buf][lr    ][rb];   ah[1] = Ah[buf][lr    ][rb + 8];
            ah[2] = Ah[buf][4 + lr][rb];   ah[3] = Ah[buf][4 + lr][rb + 8];
            al[0] = Al[buf][lr    ][rb];   al[1] = Al[buf][lr    ][rb + 8];
            al[2] = Al[buf][4 + lr][rb];   al[3] = Al[buf][4 + lr][rb + 8];
            #pragma unroll
            for (int nt = 0; nt < 4; nt++) {
                mma8(acc[mt][nt], ah, bh[nt]);
                mma8(acc[mt][nt], ah, bl[nt]);
                mma8(acc[mt][nt], al, bh[nt]);
            }
        }
        __syncthreads();
    }

    #pragma unroll
    for (int mt = 0; mt < 4; mt++) {
        const int o = o0 + wr + mt*16 + lq;
        const float bi0 = bias[o], bi1 = bias[o+8];
        #pragma unroll
        for (int nt = 0; nt < 4; nt++) {
            const int n = n0 + wc + nt*8 + 2*lr;
            float2 v0, v1;
            v0.x = __uint_as_float(f2tf((acc[mt][nt][0] + bi0) * outScale));
            v0.y = __uint_as_float(f2tf((acc[mt][nt][1] + bi0) * outScale));
            v1.x = __uint_as_float(f2tf((acc[mt][nt][2] + bi1) * outScale));
            v1.y = __uint_as_float(f2tf((acc[mt][nt][3] + bi1) * outScale));
            *(float2*)(O + (size_t)o*NTOK + n)     = v0;
            *(float2*)(O + (size_t)(o+8)*NTOK + n) = v1;
        }
    }
}

// ---------------- output projection + residual; cp.async 2-stage -----------
__global__ void __launch_bounds__(256)
mm_proj(const float* __restrict__ bias,
        const float* __restrict__ Xbase,
        float* __restrict__ Obase)
{
    const int b  = blockIdx.z;
    const unsigned* Wh  = g_wth + 3*CCH*CCH;
    const unsigned* Wl  = g_wtl + 3*CCH*CCH;
    const unsigned* Bhg = g_hvh + (size_t)b*CCH*NTOK;
    const unsigned* Blg = g_hvl + (size_t)b*CCH*NTOK;
    const float* X = Xbase + (size_t)b*CCH*NTOK;
    float*       O = Obase + (size_t)b*CCH*NTOK;
    const int o0 = blockIdx.y * 128;
    const int n0 = blockIdx.x * 128;

    __shared__ unsigned Ah[2][8][136], Al[2][8][136];
    __shared__ unsigned Bh[2][8][136], Bl[2][8][136];

    const int tid  = threadIdx.x;
    const int lane = tid & 31;
    const int wid  = tid >> 5;
    const int wr   = (wid & 1) * 64;
    const int wc   = (wid >> 1) * 32;
    const int lq   = lane >> 2;
    const int lr   = lane & 3;

    const int kc = tid >> 5, c4 = (tid & 31) * 4;

    float acc[4][4][4] = {};

    cpa16(&Ah[0][kc][c4], Wh  + kc*CCH + o0 + c4);
    cpa16(&Al[0][kc][c4], Wl  + kc*CCH + o0 + c4);
    cpa16(&Bh[0][kc][c4], Bhg + (size_t)kc*NTOK + n0 + c4);
    cpa16(&Bl[0][kc][c4], Blg + (size_t)kc*NTOK + n0 + c4);
    CPA_COMMIT;

    for (int it = 0; it < 32; it++) {
        const int buf = it & 1;
        CPA_WAIT0;
        __syncthreads();
        if (it + 1 < 32) {
            const int k0 = (it + 1) * 8;
            cpa16(&Ah[buf^1][kc][c4], Wh  + (k0+kc)*CCH + o0 + c4);
            cpa16(&Al[buf^1][kc][c4], Wl  + (k0+kc)*CCH + o0 + c4);
            cpa16(&Bh[buf^1][kc][c4], Bhg + (size_t)(k0+kc)*NTOK + n0 + c4);
            cpa16(&Bl[buf^1][kc][c4], Blg + (size_t)(k0+kc)*NTOK + n0 + c4);
            CPA_COMMIT;
        }
        unsigned bh[4][2], bl[4][2];
        #pragma unroll
        for (int nt = 0; nt < 4; nt++) {
            int col = wc + nt*8 + lq;
            bh[nt][0] = Bh[buf][lr    ][col];
            bh[nt][1] = Bh[buf][4 + lr][col];
            bl[nt][0] = Bl[buf][lr    ][col];
            bl[nt][1] = Bl[buf][4 + lr][col];
        }
        #pragma unroll
        for (int mt = 0; mt < 4; mt++) {
            unsigned ah[4], al[4];
            int rb = wr + mt*16 + lq;
            ah[0] = Ah[buf][lr    ][rb];   ah[1] = Ah[buf][lr    ][rb + 8];
            ah[2] = Ah[buf][4 + lr][rb];   ah[3] = Ah[buf][4 + lr][rb + 8];
            al[0] = Al[buf][lr    ][rb];   al[1] = Al[buf][lr    ][rb + 8];
            al[2] = Al[buf][4 + lr][rb];   al[3] = Al[buf][4 + lr][rb + 8];
            #pragma unroll
            for (int nt = 0; nt < 4; nt++) {
                mma8(acc[mt][nt], ah, bh[nt]);
                mma8(acc[mt][nt], ah, bl[nt]);
                mma8(acc[mt][nt], al, bh[nt]);
            }
        }
        __syncthreads();
    }

    #pragma unroll
    for (int mt = 0; mt < 4; mt++) {
        const int o = o0 + wr + mt*16 + lq;
        const float bi0 = bias[o], bi1 = bias[o+8];
        #pragma unroll
        for (int nt = 0; nt < 4; nt++) {
            const int n = n0 + wc + nt*8 + 2*lr;
            float2 x0 = *(const float2*)(X + (size_t)o*NTOK + n);
            float2 x1 = *(const float2*)(X + (size_t)(o+8)*NTOK + n);
            float2 v0, v1;
            v0.x = acc[mt][nt][0] + bi0 + x0.x;  v0.y = acc[mt][nt][1] + bi0 + x0.y;
            v1.x = acc[mt][nt][2] + bi1 + x1.x;  v1.y = acc[mt][nt][3] + bi1 + x1.y;
            *(float2*)(O + (size_t)o*NTOK + n)     = v0;
            *(float2*)(O + (size_t)(o+8)*NTOK + n) = v1;
        }
    }
}

// ---------------- E[n][m] = exp(q^T k); 2-stage, single sync per iter ------
__global__ void __launch_bounds__(256, 2)
mm_s_tf32(float* __restrict__ E)
{
    const int b = blockIdx.z;
    const unsigned* Q  = (const unsigned*)g_q + (size_t)b*CCH*NTOK;
    const unsigned* Kp = (const unsigned*)g_k + (size_t)b*CCH*NTOK;
    float*          Eb = E + (size_t)b*NTOK*NTOK;
    const int n0 = blockIdx.y * 128;
    const int m0 = blockIdx.x * 128;

    __shared__ unsigned As[2][16][136];   // [buf][k][n]
    __shared__ unsigned Bs[2][16][136];   // [buf][k][m]

    const int tid  = threadIdx.x;
    const int lane = tid & 31;
    const int wid  = tid >> 5;
    const int wr   = (wid & 1) * 64;
    const int wc   = (wid >> 1) * 32;
    const int lq   = lane >> 2;
    const int lr   = lane & 3;

    const int lkc0 = tid >> 5,        lc4 = (tid & 31) * 4;
    const int lkc1 = (tid + 256) >> 5;

    float acc[4][4][4] = {};

    {
        cpa16(&As[0][lkc0][lc4], Q  + (size_t)lkc0*NTOK + n0 + lc4);
        cpa16(&Bs[0][lkc0][lc4], Kp + (size_t)lkc0*NTOK + m0 + lc4);
        cpa16(&As[0][lkc1][lc4], Q  + (size_t)lkc1*NTOK + n0 + lc4);
        cpa16(&Bs[0][lkc1][lc4], Kp + (size_t)lkc1*NTOK + m0 + lc4);
        CPA_COMMIT;
    }

    for (int it = 0; it < 16; it++) {
        const int buf = it & 1;
        CPA_WAIT0;
        __syncthreads();
        if (it + 1 < 16) {
            const int k0 = (it + 1) * 16;
            cpa16(&As[buf^1][lkc0][lc4], Q  + (size_t)(k0+lkc0)*NTOK + n0 + lc4);
            cpa16(&Bs[buf^1][lkc0][lc4], Kp + (size_t)(k0+lkc0)*NTOK + m0 + lc4);
            cpa16(&As[buf^1][lkc1][lc4], Q  + (size_t)(k0+lkc1)*NTOK + n0 + lc4);
            cpa16(&Bs[buf^1][lkc1][lc4], Kp + (size_t)(k0+lkc1)*NTOK + m0 + lc4);
            CPA_COMMIT;
        }
        #pragma unroll
        for (int kk = 0; kk < 16; kk += 8) {
            unsigned bfr[4][2];
            #pragma unroll
            for (int nt = 0; nt < 4; nt++) {
                int col = wc + nt*8 + lq;
                bfr[nt][0] = Bs[buf][kk + lr    ][col];
                bfr[nt][1] = Bs[buf][kk + 4 + lr][col];
            }
            #pragma unroll
            for (int mt = 0; mt < 4; mt++) {
                unsigned afr[4];
                int rb = wr + mt*16 + lq;
                afr[0] = As[buf][kk + lr    ][rb];
                afr[1] = As[buf][kk + lr    ][rb + 8];
                afr[2] = As[buf][kk + 4 + lr][rb];
                afr[3] = As[buf][kk + 4 + lr][rb + 8];
                #pragma unroll
                for (int nt = 0; nt < 4; nt++)
                    mma8(acc[mt][nt], afr, bfr[nt]);
            }
        }
        __syncthreads();
    }

    #pragma unroll
    for (int mt = 0; mt < 4; mt++) {
        const size_t n = n0 + wr + mt*16 + lq;
        float rs0 = 0.f, rs1 = 0.f;
        #pragma unroll
        for (int nt = 0; nt < 4; nt++) {
            const int m = m0 + wc + nt*8 + 2*lr;
            float2 v0, v1;
            v0.x = __uint_as_float(f2tf(__expf(acc[mt][nt][0])));
            v0.y = __uint_as_float(f2tf(__expf(acc[mt][nt][1])));
            v1.x = __uint_as_float(f2tf(__expf(acc[mt][nt][2])));
            v1.y = __uint_as_float(f2tf(__expf(acc[mt][nt][3])));
            rs0 += v0.x + v0.y;
            rs1 += v1.x + v1.y;
            *(float2*)(Eb + n*NTOK + m)     = v0;
            *(float2*)(Eb + (n+8)*NTOK + m) = v1;
        }
        rs0 += __shfl_xor_sync(0xffffffffu, rs0, 1);
        rs0 += __shfl_xor_sync(0xffffffffu, rs0, 2);
        rs1 += __shfl_xor_sync(0xffffffffu, rs1, 1);
        rs1 += __shfl_xor_sync(0xffffffffu, rs1, 2);
        if (lr == 0) {
            atomicAdd(&g_sum[b*NTOK + n],     rs0);
            atomicAdd(&g_sum[b*NTOK + n + 8], rs1);
        }
    }
}

// ---------------- hv[c][n] = inv[n]*sum_m V[c][m]*E[n][m]; 3-stage ---------
// fused: wout emission from staged E tiles; inv computed in-kernel from g_sum
__global__ void __launch_bounds__(256)
mm_av_tf32(const float* __restrict__ E, float* __restrict__ WoutBase, int doW)
{
    const int b = blockIdx.z;
    const unsigned* V  = (const unsigned*)g_v + (size_t)b*CCH*NTOK;
    const unsigned* Eb = (const unsigned*)E   + (size_t)b*NTOK*NTOK;
    unsigned* Oh = g_hvh + (size_t)b*CCH*NTOK;
    unsigned* Ol = g_hvl + (size_t)b*CCH*NTOK;
    float*    Wb = WoutBase + (size_t)b*NTOK*NTOK;
    const int c0 = blockIdx.y * 64;
    const int n0 = blockIdx.x * 128;
    const int myPhase = blockIdx.y;

    __shared__ unsigned As[3][64][20];    // [stage][c][k]  (V)
    __shared__ unsigned Bs[3][128][20];   // [stage][n][k]  (E)
    __shared__ float    invs[128];

    const int tid  = threadIdx.x;
    const int lane = tid & 31;
    const int wid  = tid >> 5;
    const int wr   = (wid & 1) * 32;
    const int wc   = (wid >> 1) * 32;
    const int lq   = lane >> 2;
    const int lr   = lane & 3;

    const int vc  = tid >> 2,  vk4 = (tid & 3) * 4;
    const int en0 = tid >> 2;
    const int en1 = (tid + 256) >> 2;

    const int tn = tid & 127;
    const int tk = (tid >> 7) * 8;

    if (tid < 128) invs[tid] = 1.f / g_sum[b*NTOK + n0 + tid];   // fused inv

    float acc[2][4][4] = {};

    #pragma unroll
    for (int s = 0; s < 2; s++) {
        const int m0i = s * 16;
        cpa16(&As[s][vc][vk4],  V  + (size_t)(c0+vc)*NTOK + m0i + vk4);
        cpa16(&Bs[s][en0][vk4], Eb + (size_t)(n0+en0)*NTOK + m0i + vk4);
        cpa16(&Bs[s][en1][vk4], Eb + (size_t)(n0+en1)*NTOK + m0i + vk4);
        CPA_COMMIT;
    }

    for (int it = 0; it < 256; it++) {
        const int buf = it % 3;
        if (it + 1 < 256) { CPA_WAIT1; } else { CPA_WAIT0; }
        __syncthreads();
        if (it + 2 < 256) {
            const int st  = (it + 2) % 3;
            const int m0i = (it + 2) * 16;
            cpa16(&As[st][vc][vk4],  V  + (size_t)(c0+vc)*NTOK + m0i + vk4);
            cpa16(&Bs[st][en0][vk4], Eb + (size_t)(n0+en0)*NTOK + m0i + vk4);
            cpa16(&Bs[st][en1][vk4], Eb + (size_t)(n0+en1)*NTOK + m0i + vk4);
            CPA_COMMIT;
        }
        #pragma unroll
        for (int kk = 0; kk < 16; kk += 8) {
            unsigned bfr[4][2];
            #pragma unroll
            for (int nt = 0; nt < 4; nt++) {
                int col = wc + nt*8 + lq;
                bfr[nt][0] = Bs[buf][col][kk + lr];
                bfr[nt][1] = Bs[buf][col][kk + 4 + lr];
            }
            #pragma unroll
            for (int mt = 0; mt < 2; mt++) {
                unsigned afr[4];
                int rb = wr + mt*16 + lq;
                afr[0] = As[buf][rb    ][kk + lr];
                afr[1] = As[buf][rb + 8][kk + lr];
                afr[2] = As[buf][rb    ][kk + 4 + lr];
                afr[3] = As[buf][rb + 8][kk + 4 + lr];
                #pragma unroll
                for (int nt = 0; nt < 4; nt++)
                    mma8(acc[mt][nt], afr, bfr[nt]);
            }
        }
        if (doW && (it & 3) == myPhase) {
            const float iv = invs[tn];
            float* wrow = Wb + (size_t)(it*16) * NTOK + n0 + tn;
            #pragma unroll
            for (int j = 0; j < 8; j++) {
                float e = __uint_as_float(Bs[buf][tn][tk + j]);
                wrow[(size_t)(tk + j) * NTOK] = e * iv;
            }
        }
    }

    #pragma unroll
    for (int mt = 0; mt < 2; mt++) {
        const int row = wr + mt*16 + lq;
        #pragma unroll
        for (int nt = 0; nt < 4; nt++) {
            const int nl = wc + nt*8 + 2*lr;
            const float i0 = invs[nl], i1 = invs[nl+1];
            float vv[4];
            vv[0] = acc[mt][nt][0] * i0;  vv[1] = acc[mt][nt][1] * i1;
            vv[2] = acc[mt][nt][2] * i0;  vv[3] = acc[mt][nt][3] * i1;
            unsigned h0 = f2tf(vv[0]), h1 = f2tf(vv[1]);
            unsigned h2 = f2tf(vv[2]), h3 = f2tf(vv[3]);
            uint2 uh0 = {h0, h1}, uh1 = {h2, h3};
            uint2 ul0 = {f2tf(vv[0]-__uint_as_float(h0)), f2tf(vv[1]-__uint_as_float(h1))};
            uint2 ul1 = {f2tf(vv[2]-__uint_as_float(h2)), f2tf(vv[3]-__uint_as_float(h3))};
            *(uint2*)(Oh + (size_t)(c0+row  )*NTOK + n0 + nl) = uh0;
            *(uint2*)(Oh + (size_t)(c0+row+8)*NTOK + n0 + nl) = uh1;
            *(uint2*)(Ol + (size_t)(c0+row  )*NTOK + n0 + nl) = ul0;
            *(uint2*)(Ol + (size_t)(c0+row+8)*NTOK + n0 + nl) = ul1;
        }
    }
}

// ---------------------------------------------------------------------------
extern "C" void kernel_launch(void* const* d_in, const int* in_sizes, int n_in,
                              void* d_out, int out_size)
{
    const float* x     = (const float*)d_in[0];
    const float* gamma = (const float*)d_in[1];
    const float* beta  = (const float*)d_in[2];
    const float* wq = (const float*)d_in[3];  const float* bq = (const float*)d_in[4];
    const float* wk = (const float*)d_in[5];  const float* bk = (const float*)d_in[6];
    const float* wv = (const float*)d_in[7];  const float* bv = (const float*)d_in[8];
    const float* wp = (const float*)d_in[9];  const float* bp = (const float*)d_in[10];

    float* out  = (float*)d_out;                              // (2,256,4096)
    float* wout = out + (size_t)BATCH*CCH*NTOK;               // (2,4096,4096)

    float *p_p;
    cudaGetSymbolAddress((void**)&p_p, g_p);

    const int doW = out_size >= (int)((size_t)BATCH*CCH*NTOK + (size_t)BATCH*NTOK*NTOK);

    // 0. weight transpose+split (also zeroes g_sum/g_stats)
    prep_w<<<dim3(CCH, 4), CCH>>>(wq, wk, wv, wp);

    // 1. GroupNorm (two-pass; pass 2 writes tf32 hi/lo directly)
    gn_stats<<<BATCH*GRP*8, 256>>>(x);
    gn_apply<<<BATCH*CCH, 256>>>(x, gamma, beta);

    // 2. fused q/k/v projections (pipelined, cvt-free 3xTF32 split)
    mm_qkv<<<dim3(32, 6, BATCH), 256>>>(bq, bk, bv);

    // 3. E = exp(q^T k) with fused row sums (single-sync pipeline)
    mm_s_tf32<<<dim3(32, 32, BATCH), 256>>>(p_p);

    // 4+5. hv = (v . E^T)*inv AND wout = E^T*inv (fused; inv from g_sum)
    mm_av_tf32<<<dim3(32, 4, BATCH), 256>>>(p_p, wout, doW);

    // 6. out = x + (wp . hv + bp)  (pipelined, cvt-free 3xTF32 split)
    mm_proj<<<dim3(32, 2, BATCH), 256>>>(bp, x, out);
}

// round 16
// speedup vs baseline: 1.4597x; 1.4597x over previous
#include <cuda_runtime.h>
#include <cstdint>

#define NTOK 4096            // d*h*w = 16^3
#define CCH  256             // channels
#define BATCH 2
#define GRP  32
#define CPG  (CCH/GRP)       // 8
#define EPSV 1e-6f
#define SCALE 0.0625f        // 256^-0.5

// ---------------- scratch (device globals; no allocation allowed) ----------
__device__ unsigned g_hnh[BATCH*CCH*NTOK];        // tf32 split of groupnorm out
__device__ unsigned g_hnl[BATCH*CCH*NTOK];
__device__ float    g_q [BATCH*CCH*NTOK];         // tf32-rounded, pre-scaled
__device__ float    g_k [BATCH*CCH*NTOK];         // tf32-rounded
__device__ float    g_v [BATCH*CCH*NTOK];         // tf32-rounded
__device__ unsigned g_hvh[BATCH*CCH*NTOK];        // tf32 split of v.attn^T
__device__ unsigned g_hvl[BATCH*CCH*NTOK];
__device__ unsigned g_wth[4*CCH*CCH];             // W transposed [k][o], tf32 hi
__device__ unsigned g_wtl[4*CCH*CCH];             //                      tf32 lo
__device__ float    g_p [(size_t)BATCH*NTOK*NTOK]; // exp(S), tf32-rounded
__device__ float    g_sum[BATCH*NTOK];
__device__ float    g_stats[BATCH*GRP*2];

// ---------------- helpers --------------------------------------------------
__device__ __forceinline__ unsigned f2tf(float f) {
    unsigned u;
    asm("cvt.rna.tf32.f32 %0, %1;" : "=r"(u) : "f"(f));
    return u;
}

__device__ __forceinline__ void mma8(float* c, const unsigned* a, const unsigned* b) {
    asm volatile(
        "mma.sync.aligned.m16n8k8.row.col.f32.tf32.tf32.f32 "
        "{%0,%1,%2,%3}, {%4,%5,%6,%7}, {%8,%9}, {%0,%1,%2,%3};\n"
        : "+f"(c[0]), "+f"(c[1]), "+f"(c[2]), "+f"(c[3])
        : "r"(a[0]), "r"(a[1]), "r"(a[2]), "r"(a[3]),
          "r"(b[0]), "r"(b[1]));
}

__device__ __forceinline__ void cpa16(void* smem, const void* gmem) {
    unsigned saddr = (unsigned)__cvta_generic_to_shared(smem);
    asm volatile("cp.async.cg.shared.global [%0], [%1], 16;\n" :: "r"(saddr), "l"(gmem));
}
#define CPA_COMMIT asm volatile("cp.async.commit_group;\n" ::: "memory")
#define CPA_WAIT1  asm volatile("cp.async.wait_group 1;\n" ::: "memory")
#define CPA_WAIT0  asm volatile("cp.async.wait_group 0;\n" ::: "memory")

// ---------------- W prep: transpose+split; also zeros accumulators ---------
__global__ void prep_w(const float* __restrict__ w0, const float* __restrict__ w1,
                       const float* __restrict__ w2, const float* __restrict__ w3)
{
    const int m = blockIdx.y;
    const float* W = (m == 0) ? w0 : (m == 1) ? w1 : (m == 2) ? w2 : w3;
    const int o = blockIdx.x;
    const int k = threadIdx.x;
    if (m == 0) {                          // fused zeroing (idx covers 0..65535)
        const int idx = o*256 + k;
        if (idx < BATCH*NTOK)  g_sum[idx]   = 0.f;
        if (idx < BATCH*GRP*2) g_stats[idx] = 0.f;
    }
    const float f = W[o*CCH + k];
    const unsigned h = f2tf(f);
    g_wth[m*CCH*CCH + k*CCH + o] = h;
    g_wtl[m*CCH*CCH + k*CCH + o] = f2tf(f - __uint_as_float(h));
}

// ---------------- GroupNorm pass 1: partial stats --------------------------
__global__ void gn_stats(const float* __restrict__ x)
{
    const int gidx  = blockIdx.x >> 3;
    const int chunk = blockIdx.x & 7;
    const float* xp = x + (size_t)gidx*CPG*NTOK + chunk*NTOK;
    const int tid = threadIdx.x;

    float s = 0.f, ss = 0.f;
    #pragma unroll
    for (int i = tid*4; i < NTOK; i += 1024) {
        float4 t = *(const float4*)(xp + i);
        s  += t.x + t.y + t.z + t.w;
        ss += t.x*t.x + t.y*t.y + t.z*t.z + t.w*t.w;
    }
    __shared__ float rs[256], rq[256];
    rs[tid] = s; rq[tid] = ss;
    __syncthreads();
    for (int off = 128; off; off >>= 1) {
        if (tid < off) { rs[tid] += rs[tid+off]; rq[tid] += rq[tid+off]; }
        __syncthreads();
    }
    if (tid == 0) {
        atomicAdd(&g_stats[2*gidx],   rs[0]);
        atomicAdd(&g_stats[2*gidx+1], rq[0]);
    }
}

// ---------------- GroupNorm pass 2: normalize + tf32-split write -----------
__global__ void gn_apply(const float* __restrict__ x,
                         const float* __restrict__ gamma,
                         const float* __restrict__ beta)
{
    const int c    = blockIdx.x & 255;
    const int gidx = (blockIdx.x >> 8) * GRP + (c >> 3);
    const float mu   = g_stats[2*gidx]   * (1.f/32768.f);
    const float var  = g_stats[2*gidx+1] * (1.f/32768.f) - mu*mu;
    const float rstd = rsqrtf(var + EPSV);
    const float ga = gamma[c]*rstd, be = beta[c];

    const size_t base = (size_t)blockIdx.x * NTOK;
    const int i = threadIdx.x * 4;
    #pragma unroll
    for (int s = 0; s < 4; s++) {
        float4 t = *(const float4*)(x + base + i + s*1024);
        float f[4];
        f[0] = (t.x - mu)*ga + be;
        f[1] = (t.y - mu)*ga + be;
        f[2] = (t.z - mu)*ga + be;
        f[3] = (t.w - mu)*ga + be;
        uint4 uh, ul;
        uh.x = f2tf(f[0]); ul.x = f2tf(f[0] - __uint_as_float(uh.x));
        uh.y = f2tf(f[1]); ul.y = f2tf(f[1] - __uint_as_float(uh.y));
        uh.z = f2tf(f[2]); ul.z = f2tf(f[2] - __uint_as_float(uh.z));
        uh.w = f2tf(f[3]); ul.w = f2tf(f[3] - __uint_as_float(uh.w));
        *(uint4*)(g_hnh + base + i + s*1024) = uh;
        *(uint4*)(g_hnl + base + i + s*1024) = ul;
    }
}

// ---------------- fused q/k/v projection, cvt-free 3xTF32 split ------------
// (round-13 proven form: synchronous uint4 loads, k-chunk 16)
__global__ void __launch_bounds__(256)
mm_qkv(const float* __restrict__ bq,
       const float* __restrict__ bk,
       const float* __restrict__ bv)
{
    const int b   = blockIdx.z;
    const int sel = blockIdx.y >> 1;
    const int o0  = (blockIdx.y & 1) * 128;
    const int n0  = blockIdx.x * 128;

    const unsigned* Wh  = g_wth + sel*CCH*CCH;
    const unsigned* Wl  = g_wtl + sel*CCH*CCH;
    const unsigned* Bhg = g_hnh + (size_t)b*CCH*NTOK;
    const unsigned* Blg = g_hnl + (size_t)b*CCH*NTOK;
    float* O = ((sel == 0) ? g_q : (sel == 1) ? g_k : g_v) + (size_t)b*CCH*NTOK;
    const float* bias = (sel == 0) ? bq : (sel == 1) ? bk : bv;
    const float outScale = (sel == 0) ? SCALE : 1.f;

    __shared__ unsigned Ah[16][136], Al[16][136];
    __shared__ unsigned Bh[16][136], Bl[16][136];

    const int tid  = threadIdx.x;
    const int lane = tid & 31;
    const int wid  = tid >> 5;
    const int wr   = (wid & 1) * 64;
    const int wc   = (wid >> 1) * 32;
    const int lq   = lane >> 2;
    const int lr   = lane & 3;

    float acc[4][4][4] = {};

    for (int k0 = 0; k0 < CCH; k0 += 16) {
        #pragma unroll
        for (int s = 0; s < 2; s++) {
            int idx = tid + s*256;
            int kc = idx >> 5, c4 = (idx & 31) * 4;
            *(uint4*)&Ah[kc][c4] = *(const uint4*)(Wh  + (k0+kc)*CCH  + o0 + c4);
            *(uint4*)&Al[kc][c4] = *(const uint4*)(Wl  + (k0+kc)*CCH  + o0 + c4);
            *(uint4*)&Bh[kc][c4] = *(const uint4*)(Bhg + (size_t)(k0+kc)*NTOK + n0 + c4);
            *(uint4*)&Bl[kc][c4] = *(const uint4*)(Blg + (size_t)(k0+kc)*NTOK + n0 + c4);
        }
        __syncthreads();
        #pragma unroll
        for (int kk = 0; kk < 16; kk += 8) {
            unsigned bh[4][2], bl[4][2];
            #pragma unroll
            for (int nt = 0; nt < 4; nt++) {
                int col = wc + nt*8 + lq;
                bh[nt][0] = Bh[kk + lr    ][col];
                bh[nt][1] = Bh[kk + 4 + lr][col];
                bl[nt][0] = Bl[kk + lr    ][col];
                bl[nt][1] = Bl[kk + 4 + lr][col];
            }
            #pragma unroll
            for (int mt = 0; mt < 4; mt++) {
                unsigned ah[4], al[4];
                int rb = wr + mt*16 + lq;
                ah[0] = Ah[kk + lr    ][rb];   ah[1] = Ah[kk + lr    ][rb + 8];
                ah[2] = Ah[kk + 4 + lr][rb];   ah[3] = Ah[kk + 4 + lr][rb + 8];
                al[0] = Al[kk + lr    ][rb];   al[1] = Al[kk + lr    ][rb + 8];
                al[2] = Al[kk + 4 + lr][rb];   al[3] = Al[kk + 4 + lr][rb + 8];
                #pragma unroll
                for (int nt = 0; nt < 4; nt++) {
                    mma8(acc[mt][nt], ah, bh[nt]);
                    mma8(acc[mt][nt], ah, bl[nt]);
                    mma8(acc[mt][nt], al, bh[nt]);
                }
            }
        }
        __syncthreads();
    }

    #pragma unroll
    for (int mt = 0; mt < 4; mt++) {
        const int o = o0 + wr + mt*16 + lq;
        const float bi0 = bias[o], bi1 = bias[o+8];
        #pragma unroll
        for (int nt = 0; nt < 4; nt++) {
            const int n = n0 + wc + nt*8 + 2*lr;
            float2 v0, v1;
            v0.x = __uint_as_float(f2tf((acc[mt][nt][0] + bi0) * outScale));
            v0.y = __uint_as_float(f2tf((acc[mt][nt][1] + bi0) * outScale));
            v1.x = __uint_as_float(f2tf((acc[mt][nt][2] + bi1) * outScale));
            v1.y = __uint_as_float(f2tf((acc[mt][nt][3] + bi1) * outScale));
            *(float2*)(O + (size_t)o*NTOK + n)     = v0;
            *(float2*)(O + (size_t)(o+8)*NTOK + n) = v1;
        }
    }
}

// ---------------- output projection + residual (round-13 form) -------------
__global__ void __launch_bounds__(256)
mm_proj(const float* __restrict__ bias,
        const float* __restrict__ Xbase,
        float* __restrict__ Obase)
{
    const int b  = blockIdx.z;
    const unsigned* Wh  = g_wth + 3*CCH*CCH;
    const unsigned* Wl  = g_wtl + 3*CCH*CCH;
    const unsigned* Bhg = g_hvh + (size_t)b*CCH*NTOK;
    const unsigned* Blg = g_hvl + (size_t)b*CCH*NTOK;
    const float* X = Xbase + (size_t)b*CCH*NTOK;
    float*       O = Obase + (size_t)b*CCH*NTOK;
    const int o0 = blockIdx.y * 128;
    const int n0 = blockIdx.x * 128;

    __shared__ unsigned Ah[16][136], Al[16][136];
    __shared__ unsigned Bh[16][136], Bl[16][136];

    const int tid  = threadIdx.x;
    const int lane = tid & 31;
    const int wid  = tid >> 5;
    const int wr   = (wid & 1) * 64;
    const int wc   = (wid >> 1) * 32;
    const int lq   = lane >> 2;
    const int lr   = lane & 3;

    float acc[4][4][4] = {};

    for (int k0 = 0; k0 < CCH; k0 += 16) {
        #pragma unroll
        for (int s = 0; s < 2; s++) {
            int idx = tid + s*256;
            int kc = idx >> 5, c4 = (idx & 31) * 4;
            *(uint4*)&Ah[kc][c4] = *(const uint4*)(Wh  + (k0+kc)*CCH  + o0 + c4);
            *(uint4*)&Al[kc][c4] = *(const uint4*)(Wl  + (k0+kc)*CCH  + o0 + c4);
            *(uint4*)&Bh[kc][c4] = *(const uint4*)(Bhg + (size_t)(k0+kc)*NTOK + n0 + c4);
            *(uint4*)&Bl[kc][c4] = *(const uint4*)(Blg + (size_t)(k0+kc)*NTOK + n0 + c4);
        }
        __syncthreads();
        #pragma unroll
        for (int kk = 0; kk < 16; kk += 8) {
            unsigned bh[4][2], bl[4][2];
            #pragma unroll
            for (int nt = 0; nt < 4; nt++) {
                int col = wc + nt*8 + lq;
                bh[nt][0] = Bh[kk + lr    ][col];
                bh[nt][1] = Bh[kk + 4 + lr][col];
                bl[nt][0] = Bl[kk + lr    ][col];
                bl[nt][1] = Bl[kk + 4 + lr][col];
            }
            #pragma unroll
            for (int mt = 0; mt < 4; mt++) {
                unsigned ah[4], al[4];
                int rb = wr + mt*16 + lq;
                ah[0] = Ah[kk + lr    ][rb];   ah[1] = Ah[kk + lr    ][rb + 8];
                ah[2] = Ah[kk + 4 + lr][rb];   ah[3] = Ah[kk + 4 + lr][rb + 8];
                al[0] = Al[kk + lr    ][rb];   al[1] = Al[kk + lr    ][rb + 8];
                al[2] = Al[kk + 4 + lr][rb];   al[3] = Al[kk + 4 + lr][rb + 8];
                #pragma unroll
                for (int nt = 0; nt < 4; nt++) {
                    mma8(acc[mt][nt], ah, bh[nt]);
                    mma8(acc[mt][nt], ah, bl[nt]);
                    mma8(acc[mt][nt], al, bh[nt]);
                }
            }
        }
        __syncthreads();
    }

    #pragma unroll
    for (int mt = 0; mt < 4; mt++) {
        const int o = o0 + wr + mt*16 + lq;
        const float bi0 = bias[o], bi1 = bias[o+8];
        #pragma unroll
        for (int nt = 0; nt < 4; nt++) {
            const int n = n0 + wc + nt*8 + 2*lr;
            float2 x0 = *(const float2*)(X + (size_t)o*NTOK + n);
            float2 x1 = *(const float2*)(X + (size_t)(o+8)*NTOK + n);
            float2 v0, v1;
            v0.x = acc[mt][nt][0] + bi0 + x0.x;  v0.y = acc[mt][nt][1] + bi0 + x0.y;
            v1.x = acc[mt][nt][2] + bi1 + x1.x;  v1.y = acc[mt][nt][3] + bi1 + x1.y;
            *(float2*)(O + (size_t)o*NTOK + n)     = v0;
            *(float2*)(O + (size_t)(o+8)*NTOK + n) = v1;
        }
    }
}

// ---------------- E[n][m] = exp(q^T k); cp.async, prefetch-then-WAIT1 ------
__global__ void __launch_bounds__(256, 2)
mm_s_tf32(float* __restrict__ E)
{
    const int b = blockIdx.z;
    const unsigned* Q  = (const unsigned*)g_q + (size_t)b*CCH*NTOK;
    const unsigned* Kp = (const unsigned*)g_k + (size_t)b*CCH*NTOK;
    float*          Eb = E + (size_t)b*NTOK*NTOK;
    const int n0 = blockIdx.y * 128;
    const int m0 = blockIdx.x * 128;

    __shared__ unsigned As[2][16][136];   // [buf][k][n]
    __shared__ unsigned Bs[2][16][136];   // [buf][k][m]

    const int tid  = threadIdx.x;
    const int lane = tid & 31;
    const int wid  = tid >> 5;
    const int wr   = (wid & 1) * 64;
    const int wc   = (wid >> 1) * 32;
    const int lq   = lane >> 2;
    const int lr   = lane & 3;

    const int lkc0 = tid >> 5,        lc4 = (tid & 31) * 4;
    const int lkc1 = (tid + 256) >> 5;

    float acc[4][4][4] = {};

    {
        cpa16(&As[0][lkc0][lc4], Q  + (size_t)lkc0*NTOK + n0 + lc4);
        cpa16(&Bs[0][lkc0][lc4], Kp + (size_t)lkc0*NTOK + m0 + lc4);
        cpa16(&As[0][lkc1][lc4], Q  + (size_t)lkc1*NTOK + n0 + lc4);
        cpa16(&Bs[0][lkc1][lc4], Kp + (size_t)lkc1*NTOK + m0 + lc4);
        CPA_COMMIT;
    }

    for (int it = 0; it < 16; it++) {
        const int buf = it & 1;
        if (it + 1 < 16) {
            const int k0 = (it + 1) * 16;
            cpa16(&As[buf^1][lkc0][lc4], Q  + (size_t)(k0+lkc0)*NTOK + n0 + lc4);
            cpa16(&Bs[buf^1][lkc0][lc4], Kp + (size_t)(k0+lkc0)*NTOK + m0 + lc4);
            cpa16(&As[buf^1][lkc1][lc4], Q  + (size_t)(k0+lkc1)*NTOK + n0 + lc4);
            cpa16(&Bs[buf^1][lkc1][lc4], Kp + (size_t)(k0+lkc1)*NTOK + m0 + lc4);
            CPA_COMMIT;
            CPA_WAIT1;
        } else {
            CPA_WAIT0;
        }
        __syncthreads();
        #pragma unroll
        for (int kk = 0; kk < 16; kk += 8) {
            unsigned bfr[4][2];
            #pragma unroll
            for (int nt = 0; nt < 4; nt++) {
                int col = wc + nt*8 + lq;
                bfr[nt][0] = Bs[buf][kk + lr    ][col];
                bfr[nt][1] = Bs[buf][kk + 4 + lr][col];
            }
            #pragma unroll
            for (int mt = 0; mt < 4; mt++) {
                unsigned afr[4];
                int rb = wr + mt*16 + lq;
                afr[0] = As[buf][kk + lr    ][rb];
                afr[1] = As[buf][kk + lr    ][rb + 8];
                afr[2] = As[buf][kk + 4 + lr][rb];
                afr[3] = As[buf][kk + 4 + lr][rb + 8];
                #pragma unroll
                for (int nt = 0; nt < 4; nt++)
                    mma8(acc[mt][nt], afr, bfr[nt]);
            }
        }
        __syncthreads();
    }

    #pragma unroll
    for (int mt = 0; mt < 4; mt++) {
        const size_t n = n0 + wr + mt*16 + lq;
        float rs0 = 0.f, rs1 = 0.f;
        #pragma unroll
        for (int nt = 0; nt < 4; nt++) {
            const int m = m0 + wc + nt*8 + 2*lr;
            float2 v0, v1;
            v0.x = __uint_as_float(f2tf(__expf(acc[mt][nt][0])));
            v0.y = __uint_as_float(f2tf(__expf(acc[mt][nt][1])));
            v1.x = __uint_as_float(f2tf(__expf(acc[mt][nt][2])));
            v1.y = __uint_as_float(f2tf(__expf(acc[mt][nt][3])));
            rs0 += v0.x + v0.y;
            rs1 += v1.x + v1.y;
            *(float2*)(Eb + n*NTOK + m)     = v0;
            *(float2*)(Eb + (n+8)*NTOK + m) = v1;
        }
        rs0 += __shfl_xor_sync(0xffffffffu, rs0, 1);
        rs0 += __shfl_xor_sync(0xffffffffu, rs0, 2);
        rs1 += __shfl_xor_sync(0xffffffffu, rs1, 1);
        rs1 += __shfl_xor_sync(0xffffffffu, rs1, 2);
        if (lr == 0) {
            atomicAdd(&g_sum[b*NTOK + n],     rs0);
            atomicAdd(&g_sum[b*NTOK + n + 8], rs1);
        }
    }
}

// ---------------- hv[c][n] = inv[n]*sum_m V[c][m]*E[n][m]; 3-stage ---------
// fused: wout emission from staged E tiles; inv computed in-kernel from g_sum
__global__ void __launch_bounds__(256)
mm_av_tf32(const float* __restrict__ E, float* __restrict__ WoutBase, int doW)
{
    const int b = blockIdx.z;
    const unsigned* V  = (const unsigned*)g_v + (size_t)b*CCH*NTOK;
    const unsigned* Eb = (const unsigned*)E   + (size_t)b*NTOK*NTOK;
    unsigned* Oh = g_hvh + (size_t)b*CCH*NTOK;
    unsigned* Ol = g_hvl + (size_t)b*CCH*NTOK;
    float*    Wb = WoutBase + (size_t)b*NTOK*NTOK;
    const int c0 = blockIdx.y * 64;
    const int n0 = blockIdx.x * 128;
    const int myPhase = blockIdx.y;

    __shared__ unsigned As[3][64][20];    // [stage][c][k]  (V)
    __shared__ unsigned Bs[3][128][20];   // [stage][n][k]  (E)
    __shared__ float    invs[128];

    const int tid  = threadIdx.x;
    const int lane = tid & 31;
    const int wid  = tid >> 5;
    const int wr   = (wid & 1) * 32;
    const int wc   = (wid >> 1) * 32;
    const int lq   = lane >> 2;
    const int lr   = lane & 3;

    const int vc  = tid >> 2,  vk4 = (tid & 3) * 4;
    const int en0 = tid >> 2;
    const int en1 = (tid + 256) >> 2;

    const int tn = tid & 127;
    const int tk = (tid >> 7) * 8;

    if (tid < 128) invs[tid] = 1.f / g_sum[b*NTOK + n0 + tid];   // fused inv

    float acc[2][4][4] = {};

    #pragma unroll
    for (int s = 0; s < 2; s++) {
        const int m0i = s * 16;
        cpa16(&As[s][vc][vk4],  V  + (size_t)(c0+vc)*NTOK + m0i + vk4);
        cpa16(&Bs[s][en0][vk4], Eb + (size_t)(n0+en0)*NTOK + m0i + vk4);
        cpa16(&Bs[s][en1][vk4], Eb + (size_t)(n0+en1)*NTOK + m0i + vk4);
        CPA_COMMIT;
    }

    for (int it = 0; it < 256; it++) {
        const int buf = it % 3;
        if (it + 1 < 256) { CPA_WAIT1; } else { CPA_WAIT0; }
        __syncthreads();
        if (it + 2 < 256) {
            const int st  = (it + 2) % 3;
            const int m0i = (it + 2) * 16;
            cpa16(&As[st][vc][vk4],  V  + (size_t)(c0+vc)*NTOK + m0i + vk4);
            cpa16(&Bs[st][en0][vk4], Eb + (size_t)(n0+en0)*NTOK + m0i + vk4);
            cpa16(&Bs[st][en1][vk4], Eb + (size_t)(n0+en1)*NTOK + m0i + vk4);
            CPA_COMMIT;
        }
        #pragma unroll
        for (int kk = 0; kk < 16; kk += 8) {
            unsigned bfr[4][2];
            #pragma unroll
            for (int nt = 0; nt < 4; nt++) {
                int col = wc + nt*8 + lq;
                bfr[nt][0] = Bs[buf][col][kk + lr];
                bfr[nt][1] = Bs[buf][col][kk + 4 + lr];
            }
            #pragma unroll
            for (int mt = 0; mt < 2; mt++) {
                unsigned afr[4];
                int rb = wr + mt*16 + lq;
                afr[0] = As[buf][rb    ][kk + lr];
                afr[1] = As[buf][rb + 8][kk + lr];
                afr[2] = As[buf][rb    ][kk + 4 + lr];
                afr[3] = As[buf][rb + 8][kk + 4 + lr];
                #pragma unroll
                for (int nt = 0; nt < 4; nt++)
                    mma8(acc[mt][nt], afr, bfr[nt]);
            }
        }
        if (doW && (it & 3) == myPhase) {
            const float iv = invs[tn];
            float* wrow = Wb + (size_t)(it*16) * NTOK + n0 + tn;
            #pragma unroll
            for (int j = 0; j < 8; j++) {
                float e = __uint_as_float(Bs[buf][tn][tk + j]);
                wrow[(size_t)(tk + j) * NTOK] = e * iv;
            }
        }
    }

    #pragma unroll
    for (int mt = 0; mt < 2; mt++) {
        const int row = wr + mt*16 + lq;
        #pragma unroll
        for (int nt = 0; nt < 4; nt++) {
            const int nl = wc + nt*8 + 2*lr;
            const float i0 = invs[nl], i1 = invs[nl+1];
            float vv[4];
            vv[0] = acc[mt][nt][0] * i0;  vv[1] = acc[mt][nt][1] * i1;
            vv[2] = acc[mt][nt][2] * i0;  vv[3] = acc[mt][nt][3] * i1;
            unsigned h0 = f2tf(vv[0]), h1 = f2tf(vv[1]);
            unsigned h2 = f2tf(vv[2]), h3 = f2tf(vv[3]);
            uint2 uh0 = {h0, h1}, uh1 = {h2, h3};
            uint2 ul0 = {f2tf(vv[0]-__uint_as_float(h0)), f2tf(vv[1]-__uint_as_float(h1))};
            uint2 ul1 = {f2tf(vv[2]-__uint_as_float(h2)), f2tf(vv[3]-__uint_as_float(h3))};
            *(uint2*)(Oh + (size_t)(c0+row  )*NTOK + n0 + nl) = uh0;
            *(uint2*)(Oh + (size_t)(c0+row+8)*NTOK + n0 + nl) = uh1;
            *(uint2*)(Ol + (size_t)(c0+row  )*NTOK + n0 + nl) = ul0;
            *(uint2*)(Ol + (size_t)(c0+row+8)*NTOK + n0 + nl) = ul1;
        }
    }
}

// ---------------------------------------------------------------------------
extern "C" void kernel_launch(void* const* d_in, const int* in_sizes, int n_in,
                              void* d_out, int out_size)
{
    const float* x     = (const float*)d_in[0];
    const float* gamma = (const float*)d_in[1];
    const float* beta  = (const float*)d_in[2];
    const float* wq = (const float*)d_in[3];  const float* bq = (const float*)d_in[4];
    const float* wk = (const float*)d_in[5];  const float* bk = (const float*)d_in[6];
    const float* wv = (const float*)d_in[7];  const float* bv = (const float*)d_in[8];
    const float* wp = (const float*)d_in[9];  const float* bp = (const float*)d_in[10];

    float* out  = (float*)d_out;                              // (2,256,4096)
    float* wout = out + (size_t)BATCH*CCH*NTOK;               // (2,4096,4096)

    float *p_p;
    cudaGetSymbolAddress((void**)&p_p, g_p);

    const int doW = out_size >= (int)((size_t)BATCH*CCH*NTOK + (size_t)BATCH*NTOK*NTOK);

    // 0. weight transpose+split (also zeroes g_sum/g_stats)
    prep_w<<<dim3(CCH, 4), CCH>>>(wq, wk, wv, wp);

    // 1. GroupNorm (two-pass; pass 2 writes tf32 hi/lo directly)
    gn_stats<<<BATCH*GRP*8, 256>>>(x);
    gn_apply<<<BATCH*CCH, 256>>>(x, gamma, beta);

    // 2. fused q/k/v projections (round-13 form)
    mm_qkv<<<dim3(32, 6, BATCH), 256>>>(bq, bk, bv);

    // 3. E = exp(q^T k) with fused row sums (prefetch-then-WAIT1 pipeline)
    mm_s_tf32<<<dim3(32, 32, BATCH), 256>>>(p_p);

    // 4+5. hv = (v . E^T)*inv AND wout = E^T*inv (fused; inv from g_sum)
    mm_av_tf32<<<dim3(32, 4, BATCH), 256>>>(p_p, wout, doW);

    // 6. out = x + (wp . hv + bp)  (round-13 form)
    mm_proj<<<dim3(32, 2, BATCH), 256>>>(bp, x, out);
}